// round 8
// baseline (speedup 1.0000x reference)
#include <cuda_runtime.h>
#include <cuda_fp16.h>
#include <cuda_bf16.h>

// GCN via CSR gather, fp16 feature storage, f32x2 packed-FMA GEMMs.
// Gather: warp-per-node, 8 col-lanes x 4 edge-groups (latency-hiding + no divergence).

#define NN 50000
#define NE 800000
#define HID 64

// ---- scratch (device globals; referenced only from device code) ----
__device__ __align__(16) uint2 g_hs[NN * 16];    // fp16 rows: 64 half = 128B
__device__ __align__(16) uint2 g_out1[NN * 16];  // layer-1 activations, fp16
__device__ __align__(16) float g_dinv[NN];
__device__ int   g_ideg[NN];
__device__ int   g_pos[NN];
__device__ int   g_rowstart[NN];
__device__ int   g_cursor[NN];
__device__ int   g_esrc[NE];
__device__ int   g_bsum[64];
__device__ __align__(16) float g_gbuf[128];  // [0:64) sums, [64:128) counts

// ---------------------------------------------------------------------------
// count: 4 edges/thread via int4
__global__ void k_count(const int* __restrict__ dst, int ne4) {
    int t = blockIdx.x * blockDim.x + threadIdx.x;
    if (t >= ne4) return;
    int4 d = reinterpret_cast<const int4*>(dst)[t];
    atomicAdd(&g_ideg[d.x], 1);
    atomicAdd(&g_ideg[d.y], 1);
    atomicAdd(&g_ideg[d.z], 1);
    atomicAdd(&g_ideg[d.w], 1);
}

// exclusive scan of g_ideg, 1024-chunks
__global__ __launch_bounds__(1024) void k_scan1(int n) {
    __shared__ int sh[1024];
    int i = blockIdx.x * 1024 + threadIdx.x;
    int v = (i < n) ? g_ideg[i] : 0;
    sh[threadIdx.x] = v;
    __syncthreads();
    for (int off = 1; off < 1024; off <<= 1) {
        int t = (threadIdx.x >= off) ? sh[threadIdx.x - off] : 0;
        __syncthreads();
        sh[threadIdx.x] += t;
        __syncthreads();
    }
    int incl = sh[threadIdx.x];
    if (i < n) g_pos[i] = incl - v;
    if (threadIdx.x == 1023) g_bsum[blockIdx.x] = incl;
}

// per-block: add prefix of bsums (<=64 chunks), set rowstart/cursor/dinv
__global__ __launch_bounds__(256) void k_scan3(int n) {
    __shared__ int off_sh;
    int chunk = blockIdx.x >> 2;           // 256 threads/block, 1024/chunk
    if (threadIdx.x < 32) {
        int t = threadIdx.x;
        int v = (t < chunk ? g_bsum[t] : 0) + (t + 32 < chunk ? g_bsum[t + 32] : 0);
        #pragma unroll
        for (int o = 16; o; o >>= 1) v += __shfl_xor_sync(0xFFFFFFFFu, v, o);
        if (t == 0) off_sh = v;
    }
    __syncthreads();
    int i = blockIdx.x * blockDim.x + threadIdx.x;
    if (i >= n) return;
    int base = g_pos[i] + off_sh;
    g_rowstart[i] = base;
    g_cursor[i]   = base;
    g_dinv[i]     = rsqrtf((float)g_ideg[i] + 1.0f);
}

// fill: 4 edges/thread via int4
__global__ void k_fill(const int* __restrict__ src, const int* __restrict__ dst, int ne4) {
    int t = blockIdx.x * blockDim.x + threadIdx.x;
    if (t >= ne4) return;
    int4 s = reinterpret_cast<const int4*>(src)[t];
    int4 d = reinterpret_cast<const int4*>(dst)[t];
    int p0 = atomicAdd(&g_cursor[d.x], 1);
    int p1 = atomicAdd(&g_cursor[d.y], 1);
    int p2 = atomicAdd(&g_cursor[d.z], 1);
    int p3 = atomicAdd(&g_cursor[d.w], 1);
    g_esrc[p0] = s.x;
    g_esrc[p1] = s.y;
    g_esrc[p2] = s.z;
    g_esrc[p3] = s.w;
}

// ---------------------------------------------------------------------------
// GEMM: g_hs[r,0:64](fp16) = (X[r,0:K] @ W[K,64]) * dinv[r]
template <int K, bool HALF_IN>
__global__ __launch_bounds__(256) void k_gemm(
    const float* __restrict__ Xin, const float* __restrict__ W, int nrows)
{
    __shared__ float Xs[32][132];
    __shared__ float Ws[32][64];

    const int tid  = threadIdx.x;
    const int row0 = blockIdx.x * 128;
    const int tx   = tid & 15;
    const int ty   = tid >> 4;

    unsigned long long acc2[4][4];
    #pragma unroll
    for (int p = 0; p < 4; p++)
        #pragma unroll
        for (int c = 0; c < 4; c++) acc2[p][c] = 0ull;

    for (int k0 = 0; k0 < K; k0 += 32) {
        for (int i = tid; i < 32 * 16; i += 256) {
            reinterpret_cast<float4*>(&Ws[0][0])[i] =
                reinterpret_cast<const float4*>(W + (size_t)k0 * 64)[i];
        }
        if (!HALF_IN) {
            for (int f = tid; f < 128 * 8; f += 256) {
                int r = f >> 3;
                int c = (f & 7) * 4;
                int gr = row0 + r;
                float4 v = make_float4(0.f, 0.f, 0.f, 0.f);
                if (gr < nrows)
                    v = *reinterpret_cast<const float4*>(Xin + (size_t)gr * K + k0 + c);
                Xs[c + 0][r] = v.x; Xs[c + 1][r] = v.y;
                Xs[c + 2][r] = v.z; Xs[c + 3][r] = v.w;
            }
        } else {
            const uint4* X4 = reinterpret_cast<const uint4*>(g_out1);
            for (int f = tid; f < 128 * 4; f += 256) {
                int r  = f >> 2;
                int c8 = (f & 3) * 8;
                int gr = row0 + r;
                uint4 u = make_uint4(0u, 0u, 0u, 0u);
                if (gr < nrows)
                    u = X4[(size_t)gr * 8 + (k0 >> 3) + (f & 3)];
                float2 f0 = __half22float2(*reinterpret_cast<__half2*>(&u.x));
                float2 f1 = __half22float2(*reinterpret_cast<__half2*>(&u.y));
                float2 f2 = __half22float2(*reinterpret_cast<__half2*>(&u.z));
                float2 f3 = __half22float2(*reinterpret_cast<__half2*>(&u.w));
                Xs[c8 + 0][r] = f0.x; Xs[c8 + 1][r] = f0.y;
                Xs[c8 + 2][r] = f1.x; Xs[c8 + 3][r] = f1.y;
                Xs[c8 + 4][r] = f2.x; Xs[c8 + 5][r] = f2.y;
                Xs[c8 + 6][r] = f3.x; Xs[c8 + 7][r] = f3.y;
            }
        }
        __syncthreads();

        #pragma unroll 4
        for (int kk = 0; kk < 32; kk++) {
            float4 wv = *reinterpret_cast<const float4*>(&Ws[kk][tx * 4]);
            unsigned long long w2[4];
            asm("mov.b64 %0,{%1,%1};" : "=l"(w2[0]) : "f"(wv.x));
            asm("mov.b64 %0,{%1,%1};" : "=l"(w2[1]) : "f"(wv.y));
            asm("mov.b64 %0,{%1,%1};" : "=l"(w2[2]) : "f"(wv.z));
            asm("mov.b64 %0,{%1,%1};" : "=l"(w2[3]) : "f"(wv.w));
            #pragma unroll
            for (int p = 0; p < 4; p++) {
                unsigned long long xp =
                    *reinterpret_cast<const unsigned long long*>(&Xs[kk][ty * 8 + 2 * p]);
                #pragma unroll
                for (int c = 0; c < 4; c++) {
                    asm("fma.rn.f32x2 %0,%1,%2,%0;"
                        : "+l"(acc2[p][c]) : "l"(xp), "l"(w2[c]));
                }
            }
        }
        __syncthreads();
    }

    #pragma unroll
    for (int p = 0; p < 4; p++) {
        float lo[4], hi[4];
        #pragma unroll
        for (int c = 0; c < 4; c++) {
            lo[c] = __uint_as_float((unsigned)(acc2[p][c] & 0xFFFFFFFFull));
            hi[c] = __uint_as_float((unsigned)(acc2[p][c] >> 32));
        }
        int r0 = row0 + ty * 8 + 2 * p;
        if (r0 < nrows) {
            float s = g_dinv[r0];
            __half2 h01 = __floats2half2_rn(lo[0] * s, lo[1] * s);
            __half2 h23 = __floats2half2_rn(lo[2] * s, lo[3] * s);
            uint2 u;
            u.x = *reinterpret_cast<unsigned*>(&h01);
            u.y = *reinterpret_cast<unsigned*>(&h23);
            g_hs[(size_t)r0 * 16 + tx] = u;
        }
        int r1 = r0 + 1;
        if (r1 < nrows) {
            float s = g_dinv[r1];
            __half2 h01 = __floats2half2_rn(hi[0] * s, hi[1] * s);
            __half2 h23 = __floats2half2_rn(hi[2] * s, hi[3] * s);
            uint2 u;
            u.x = *reinterpret_cast<unsigned*>(&h01);
            u.y = *reinterpret_cast<unsigned*>(&h23);
            g_hs[(size_t)r1 * 16 + tx] = u;
        }
    }
}

// ---------------------------------------------------------------------------
// Warp-per-node gather core. lane = q (0-7, col group) + 8*eg (0-3, edge group).
// Each eg handles edges beg+eg, beg+eg+4, ... ; cross-eg reduce via shfl.
__device__ __forceinline__ void acc_row8(float (&a)[8], uint4 u) {
    float2 f0 = __half22float2(*reinterpret_cast<__half2*>(&u.x));
    float2 f1 = __half22float2(*reinterpret_cast<__half2*>(&u.y));
    float2 f2 = __half22float2(*reinterpret_cast<__half2*>(&u.z));
    float2 f3 = __half22float2(*reinterpret_cast<__half2*>(&u.w));
    a[0] += f0.x; a[1] += f0.y; a[2] += f1.x; a[3] += f1.y;
    a[4] += f2.x; a[5] += f2.y; a[6] += f3.x; a[7] += f3.y;
}

__device__ __forceinline__ void gather_warp(int node, int q, int eg, float (&a)[8]) {
    const uint4* __restrict__ H = reinterpret_cast<const uint4*>(g_hs);
    int beg = g_rowstart[node];
    int end = beg + g_ideg[node];

    int j = beg + eg;
    // unroll 2: two outstanding row loads per lane
    for (; j + 4 < end; j += 8) {
        int s0 = g_esrc[j];
        int s1 = g_esrc[j + 4];
        uint4 u0 = H[(size_t)s0 * 8 + q];
        uint4 u1 = H[(size_t)s1 * 8 + q];
        acc_row8(a, u0);
        acc_row8(a, u1);
    }
    if (j < end) acc_row8(a, H[(size_t)g_esrc[j] * 8 + q]);

    if (eg == 0) acc_row8(a, H[(size_t)node * 8 + q]);   // self term

    #pragma unroll
    for (int i = 0; i < 8; i++) {
        a[i] += __shfl_xor_sync(0xFFFFFFFFu, a[i], 8);
        a[i] += __shfl_xor_sync(0xFFFFFFFFu, a[i], 16);
    }
}

// Gather layer 1 + epilogue: out1 = relu(dinv*(sum + self) + b1), fp16 store
__global__ __launch_bounds__(256) void k_gather1(const float* __restrict__ b1, int n)
{
    int node = (blockIdx.x * blockDim.x + threadIdx.x) >> 5;
    if (node >= n) return;
    int lane = threadIdx.x & 31;
    int q = lane & 7, eg = lane >> 3;

    float a[8] = {};
    gather_warp(node, q, eg, a);

    if (eg == 0) {
        float s = g_dinv[node];
        float4 bb0 = reinterpret_cast<const float4*>(b1)[2 * q];
        float4 bb1 = reinterpret_cast<const float4*>(b1)[2 * q + 1];
        __half2 h0 = __floats2half2_rn(fmaxf(0.f, s * a[0] + bb0.x),
                                       fmaxf(0.f, s * a[1] + bb0.y));
        __half2 h1 = __floats2half2_rn(fmaxf(0.f, s * a[2] + bb0.z),
                                       fmaxf(0.f, s * a[3] + bb0.w));
        __half2 h2 = __floats2half2_rn(fmaxf(0.f, s * a[4] + bb1.x),
                                       fmaxf(0.f, s * a[5] + bb1.y));
        __half2 h3 = __floats2half2_rn(fmaxf(0.f, s * a[6] + bb1.z),
                                       fmaxf(0.f, s * a[7] + bb1.w));
        uint4 u;
        u.x = *reinterpret_cast<unsigned*>(&h0);
        u.y = *reinterpret_cast<unsigned*>(&h1);
        u.z = *reinterpret_cast<unsigned*>(&h2);
        u.w = *reinterpret_cast<unsigned*>(&h3);
        reinterpret_cast<uint4*>(g_out1)[(size_t)node * 8 + q] = u;
    }
}

// Gather layer 2 + fused head: v = relu(dinv*(sum+self)+b2); dot(v,Wlin)
__global__ __launch_bounds__(256) void k_gather2(
    const float* __restrict__ b2, const float* __restrict__ Wlin,
    const int* __restrict__ batch, int n)
{
    int node = (blockIdx.x * blockDim.x + threadIdx.x) >> 5;
    if (node >= n) return;
    int lane = threadIdx.x & 31;
    int q = lane & 7, eg = lane >> 3;

    float a[8] = {};
    gather_warp(node, q, eg, a);

    float s = g_dinv[node];
    float4 bb0 = reinterpret_cast<const float4*>(b2)[2 * q];
    float4 bb1 = reinterpret_cast<const float4*>(b2)[2 * q + 1];
    float4 wl0 = reinterpret_cast<const float4*>(Wlin)[2 * q];
    float4 wl1 = reinterpret_cast<const float4*>(Wlin)[2 * q + 1];
    float dot =
        fmaxf(0.f, s * a[0] + bb0.x) * wl0.x +
        fmaxf(0.f, s * a[1] + bb0.y) * wl0.y +
        fmaxf(0.f, s * a[2] + bb0.z) * wl0.z +
        fmaxf(0.f, s * a[3] + bb0.w) * wl0.w +
        fmaxf(0.f, s * a[4] + bb1.x) * wl1.x +
        fmaxf(0.f, s * a[5] + bb1.y) * wl1.y +
        fmaxf(0.f, s * a[6] + bb1.z) * wl1.z +
        fmaxf(0.f, s * a[7] + bb1.w) * wl1.w;

    // reduce over q lanes (within eg==0 subgroup: offsets 1,2,4)
    #pragma unroll
    for (int o = 4; o; o >>= 1) dot += __shfl_xor_sync(0xFFFFFFFFu, dot, o);
    if (lane == 0) {
        int g = __ldg(batch + node);
        atomicAdd(&g_gbuf[g], dot);
        atomicAdd(&g_gbuf[64 + g], 1.0f);
    }
}

// ---------------------------------------------------------------------------
__global__ void k_finalize(const float* __restrict__ blin, float* __restrict__ out) {
    int g = threadIdx.x;
    if (g < 64) out[g] = g_gbuf[g] / fmaxf(g_gbuf[64 + g], 1.0f) + blin[0];
}

// ---------------------------------------------------------------------------
extern "C" void kernel_launch(void* const* d_in, const int* in_sizes, int n_in,
                              void* d_out, int out_size)
{
    const float* x     = (const float*)d_in[0];
    const int*   eidx  = (const int*)d_in[1];
    const int*   batch = (const int*)d_in[2];
    const float* W1    = (const float*)d_in[3];
    const float* b1    = (const float*)d_in[4];
    const float* W2    = (const float*)d_in[5];
    const float* b2    = (const float*)d_in[6];
    const float* Wlin  = (const float*)d_in[7];
    const float* blin  = (const float*)d_in[8];
    float* out = (float*)d_out;

    const int N = in_sizes[0] / 128;   // 50000
    const int E = in_sizes[1] / 2;     // 800000
    const int* src = eidx;
    const int* dst = eidx + E;

    const int T = 256;
    const int NB = (N + 1023) / 1024;
    const int E4 = E / 4;              // E divisible by 4

    void* p_ideg = nullptr;
    void* p_gbuf = nullptr;
    cudaGetSymbolAddress(&p_ideg, g_ideg);
    cudaGetSymbolAddress(&p_gbuf, g_gbuf);
    cudaMemsetAsync(p_ideg, 0, NN * sizeof(int));
    cudaMemsetAsync(p_gbuf, 0, 128 * sizeof(float));

    // CSR build + dinv
    k_count<<<(E4 + T - 1) / T, T>>>(dst, E4);
    k_scan1<<<NB, 1024>>>(N);
    k_scan3<<<(N + T - 1) / T, T>>>(N);
    k_fill <<<(E4 + T - 1) / T, T>>>(src, dst, E4);

    // layer 1
    k_gemm<128, false><<<(N + 127) / 128, 256>>>(x, W1, N);
    k_gather1<<<(N * 32 + T - 1) / T, T>>>(b1, N);

    // layer 2
    k_gemm<64, true><<<(N + 127) / 128, 256>>>(nullptr, W2, N);
    k_gather2<<<(N * 32 + T - 1) / T, T>>>(b2, Wlin, batch, N);

    k_finalize<<<1, 64>>>(blin, out);
}

// round 9
// speedup vs baseline: 1.1897x; 1.1897x over previous
#include <cuda_runtime.h>
#include <cuda_fp16.h>
#include <cuda_bf16.h>

// GCN via CSR gather, fp16 features, f32x2 GEMMs.
// Round 9: GEMM1 forked onto a second stream, parallel with CSR build.
// Layer-1 hs is UNSCALED; gather1 applies dinv[src] per edge (ES=true).

#define NN 50000
#define NE 800000
#define HID 64

__device__ __align__(16) uint2 g_hs[NN * 16];    // fp16 rows: 64 half = 128B
__device__ __align__(16) uint2 g_out1[NN * 16];  // layer-1 activations, fp16
__device__ __align__(16) float g_dinv[NN];
__device__ int   g_ideg[NN];
__device__ int   g_pos[NN];
__device__ int   g_rowstart[NN];
__device__ int   g_cursor[NN];
__device__ int   g_esrc[NE];
__device__ int   g_bsum[64];
__device__ __align__(16) float g_gbuf[128];  // [0:64) sums, [64:128) counts

// ---------------------------------------------------------------------------
__global__ void k_count(const int* __restrict__ dst, int ne) {
    int e = blockIdx.x * blockDim.x + threadIdx.x;
    if (e < ne) atomicAdd(&g_ideg[dst[e]], 1);
}

__global__ __launch_bounds__(1024) void k_scan1(int n) {
    __shared__ int sh[1024];
    int i = blockIdx.x * 1024 + threadIdx.x;
    int v = (i < n) ? g_ideg[i] : 0;
    sh[threadIdx.x] = v;
    __syncthreads();
    for (int off = 1; off < 1024; off <<= 1) {
        int t = (threadIdx.x >= off) ? sh[threadIdx.x - off] : 0;
        __syncthreads();
        sh[threadIdx.x] += t;
        __syncthreads();
    }
    int incl = sh[threadIdx.x];
    if (i < n) g_pos[i] = incl - v;
    if (threadIdx.x == 1023) g_bsum[blockIdx.x] = incl;
}

__global__ __launch_bounds__(256) void k_scan3(int n) {
    __shared__ int off_sh;
    int chunk = blockIdx.x >> 2;
    if (threadIdx.x < 32) {
        int t = threadIdx.x;
        int v = (t < chunk ? g_bsum[t] : 0) + (t + 32 < chunk ? g_bsum[t + 32] : 0);
        #pragma unroll
        for (int o = 16; o; o >>= 1) v += __shfl_xor_sync(0xFFFFFFFFu, v, o);
        if (t == 0) off_sh = v;
    }
    __syncthreads();
    int i = blockIdx.x * blockDim.x + threadIdx.x;
    if (i >= n) return;
    int base = g_pos[i] + off_sh;
    g_rowstart[i] = base;
    g_cursor[i]   = base;
    g_dinv[i]     = rsqrtf((float)g_ideg[i] + 1.0f);
}

__global__ void k_fill(const int* __restrict__ src, const int* __restrict__ dst, int ne) {
    int e = blockIdx.x * blockDim.x + threadIdx.x;
    if (e >= ne) return;
    int p = atomicAdd(&g_cursor[dst[e]], 1);
    g_esrc[p] = src[e];
}

// ---------------------------------------------------------------------------
// GEMM: g_hs[r,0:64](fp16) = (X[r,0:K] @ W[K,64]) * (SCALE ? dinv[r] : 1)
template <int K, bool HALF_IN, bool SCALE>
__global__ __launch_bounds__(256) void k_gemm(
    const float* __restrict__ Xin, const float* __restrict__ W, int nrows)
{
    __shared__ float Xs[32][132];
    __shared__ float Ws[32][64];

    const int tid  = threadIdx.x;
    const int row0 = blockIdx.x * 128;
    const int tx   = tid & 15;
    const int ty   = tid >> 4;

    unsigned long long acc2[4][4];
    #pragma unroll
    for (int p = 0; p < 4; p++)
        #pragma unroll
        for (int c = 0; c < 4; c++) acc2[p][c] = 0ull;

    for (int k0 = 0; k0 < K; k0 += 32) {
        for (int i = tid; i < 32 * 16; i += 256) {
            reinterpret_cast<float4*>(&Ws[0][0])[i] =
                reinterpret_cast<const float4*>(W + (size_t)k0 * 64)[i];
        }
        if (!HALF_IN) {
            for (int f = tid; f < 128 * 8; f += 256) {
                int r = f >> 3;
                int c = (f & 7) * 4;
                int gr = row0 + r;
                float4 v = make_float4(0.f, 0.f, 0.f, 0.f);
                if (gr < nrows)
                    v = *reinterpret_cast<const float4*>(Xin + (size_t)gr * K + k0 + c);
                Xs[c + 0][r] = v.x; Xs[c + 1][r] = v.y;
                Xs[c + 2][r] = v.z; Xs[c + 3][r] = v.w;
            }
        } else {
            const uint4* X4 = reinterpret_cast<const uint4*>(g_out1);
            for (int f = tid; f < 128 * 4; f += 256) {
                int r  = f >> 2;
                int c8 = (f & 3) * 8;
                int gr = row0 + r;
                uint4 u = make_uint4(0u, 0u, 0u, 0u);
                if (gr < nrows)
                    u = X4[(size_t)gr * 8 + (k0 >> 3) + (f & 3)];
                float2 f0 = __half22float2(*reinterpret_cast<__half2*>(&u.x));
                float2 f1 = __half22float2(*reinterpret_cast<__half2*>(&u.y));
                float2 f2 = __half22float2(*reinterpret_cast<__half2*>(&u.z));
                float2 f3 = __half22float2(*reinterpret_cast<__half2*>(&u.w));
                Xs[c8 + 0][r] = f0.x; Xs[c8 + 1][r] = f0.y;
                Xs[c8 + 2][r] = f1.x; Xs[c8 + 3][r] = f1.y;
                Xs[c8 + 4][r] = f2.x; Xs[c8 + 5][r] = f2.y;
                Xs[c8 + 6][r] = f3.x; Xs[c8 + 7][r] = f3.y;
            }
        }
        __syncthreads();

        #pragma unroll 4
        for (int kk = 0; kk < 32; kk++) {
            float4 wv = *reinterpret_cast<const float4*>(&Ws[kk][tx * 4]);
            unsigned long long w2[4];
            asm("mov.b64 %0,{%1,%1};" : "=l"(w2[0]) : "f"(wv.x));
            asm("mov.b64 %0,{%1,%1};" : "=l"(w2[1]) : "f"(wv.y));
            asm("mov.b64 %0,{%1,%1};" : "=l"(w2[2]) : "f"(wv.z));
            asm("mov.b64 %0,{%1,%1};" : "=l"(w2[3]) : "f"(wv.w));
            #pragma unroll
            for (int p = 0; p < 4; p++) {
                unsigned long long xp =
                    *reinterpret_cast<const unsigned long long*>(&Xs[kk][ty * 8 + 2 * p]);
                #pragma unroll
                for (int c = 0; c < 4; c++) {
                    asm("fma.rn.f32x2 %0,%1,%2,%0;"
                        : "+l"(acc2[p][c]) : "l"(xp), "l"(w2[c]));
                }
            }
        }
        __syncthreads();
    }

    #pragma unroll
    for (int p = 0; p < 4; p++) {
        float lo[4], hi[4];
        #pragma unroll
        for (int c = 0; c < 4; c++) {
            lo[c] = __uint_as_float((unsigned)(acc2[p][c] & 0xFFFFFFFFull));
            hi[c] = __uint_as_float((unsigned)(acc2[p][c] >> 32));
        }
        int r0 = row0 + ty * 8 + 2 * p;
        if (r0 < nrows) {
            float s = SCALE ? g_dinv[r0] : 1.0f;
            __half2 h01 = __floats2half2_rn(lo[0] * s, lo[1] * s);
            __half2 h23 = __floats2half2_rn(lo[2] * s, lo[3] * s);
            uint2 u;
            u.x = *reinterpret_cast<unsigned*>(&h01);
            u.y = *reinterpret_cast<unsigned*>(&h23);
            g_hs[(size_t)r0 * 16 + tx] = u;
        }
        int r1 = r0 + 1;
        if (r1 < nrows) {
            float s = SCALE ? g_dinv[r1] : 1.0f;
            __half2 h01 = __floats2half2_rn(hi[0] * s, hi[1] * s);
            __half2 h23 = __floats2half2_rn(hi[2] * s, hi[3] * s);
            uint2 u;
            u.x = *reinterpret_cast<unsigned*>(&h01);
            u.y = *reinterpret_cast<unsigned*>(&h23);
            g_hs[(size_t)r1 * 16 + tx] = u;
        }
    }
}

// ---------------------------------------------------------------------------
// Gather: 8 lanes/node, lane q covers cols 8q..8q+7 (one uint4 = 8 half).
// ES: rows in g_hs are unscaled; multiply each gathered row by dinv[row].
__device__ __forceinline__ void acc_row8s(float (&a)[8], uint4 u, float w) {
    float2 f0 = __half22float2(*reinterpret_cast<__half2*>(&u.x));
    float2 f1 = __half22float2(*reinterpret_cast<__half2*>(&u.y));
    float2 f2 = __half22float2(*reinterpret_cast<__half2*>(&u.z));
    float2 f3 = __half22float2(*reinterpret_cast<__half2*>(&u.w));
    a[0] = fmaf(w, f0.x, a[0]); a[1] = fmaf(w, f0.y, a[1]);
    a[2] = fmaf(w, f1.x, a[2]); a[3] = fmaf(w, f1.y, a[3]);
    a[4] = fmaf(w, f2.x, a[4]); a[5] = fmaf(w, f2.y, a[5]);
    a[6] = fmaf(w, f3.x, a[6]); a[7] = fmaf(w, f3.y, a[7]);
}

template <bool ES>
__device__ __forceinline__ void gather_core(int node, int q, float (&a)[8]) {
    const uint4* __restrict__ H = reinterpret_cast<const uint4*>(g_hs);
    int beg = g_rowstart[node];
    int end = beg + g_ideg[node];

    acc_row8s(a, H[(size_t)node * 8 + q], ES ? g_dinv[node] : 1.0f);  // self

    int j = beg;
    for (; j + 4 <= end; j += 4) {
        int s0 = g_esrc[j], s1 = g_esrc[j + 1], s2 = g_esrc[j + 2], s3 = g_esrc[j + 3];
        float w0 = ES ? g_dinv[s0] : 1.0f;
        float w1 = ES ? g_dinv[s1] : 1.0f;
        float w2 = ES ? g_dinv[s2] : 1.0f;
        float w3 = ES ? g_dinv[s3] : 1.0f;
        uint4 u0 = H[(size_t)s0 * 8 + q];
        uint4 u1 = H[(size_t)s1 * 8 + q];
        uint4 u2 = H[(size_t)s2 * 8 + q];
        uint4 u3 = H[(size_t)s3 * 8 + q];
        acc_row8s(a, u0, w0); acc_row8s(a, u1, w1);
        acc_row8s(a, u2, w2); acc_row8s(a, u3, w3);
    }
    for (; j < end; j++) {
        int s = g_esrc[j];
        acc_row8s(a, H[(size_t)s * 8 + q], ES ? g_dinv[s] : 1.0f);
    }
}

// Gather layer 1 (ES=true) + epilogue: out1 = relu(dinv*(sum) + b1), fp16 store
__global__ __launch_bounds__(256) void k_gather1(const float* __restrict__ b1, int n)
{
    int gi = blockIdx.x * blockDim.x + threadIdx.x;
    int node = gi >> 3;
    if (node >= n) return;
    int q = gi & 7;

    float a[8] = {};
    gather_core<true>(node, q, a);

    float s = g_dinv[node];
    float4 bb0 = reinterpret_cast<const float4*>(b1)[2 * q];
    float4 bb1 = reinterpret_cast<const float4*>(b1)[2 * q + 1];
    __half2 h0 = __floats2half2_rn(fmaxf(0.f, s * a[0] + bb0.x),
                                   fmaxf(0.f, s * a[1] + bb0.y));
    __half2 h1 = __floats2half2_rn(fmaxf(0.f, s * a[2] + bb0.z),
                                   fmaxf(0.f, s * a[3] + bb0.w));
    __half2 h2 = __floats2half2_rn(fmaxf(0.f, s * a[4] + bb1.x),
                                   fmaxf(0.f, s * a[5] + bb1.y));
    __half2 h3 = __floats2half2_rn(fmaxf(0.f, s * a[6] + bb1.z),
                                   fmaxf(0.f, s * a[7] + bb1.w));
    uint4 u;
    u.x = *reinterpret_cast<unsigned*>(&h0);
    u.y = *reinterpret_cast<unsigned*>(&h1);
    u.z = *reinterpret_cast<unsigned*>(&h2);
    u.w = *reinterpret_cast<unsigned*>(&h3);
    reinterpret_cast<uint4*>(g_out1)[(size_t)node * 8 + q] = u;
}

// Gather layer 2 (ES=false, hs pre-scaled) + fused head
__global__ __launch_bounds__(256) void k_gather2(
    const float* __restrict__ b2, const float* __restrict__ Wlin,
    const int* __restrict__ batch, int n)
{
    int gi = blockIdx.x * blockDim.x + threadIdx.x;
    int node = gi >> 3;
    if (node >= n) return;
    int q = gi & 7;

    float a[8] = {};
    gather_core<false>(node, q, a);

    float s = g_dinv[node];
    float4 bb0 = reinterpret_cast<const float4*>(b2)[2 * q];
    float4 bb1 = reinterpret_cast<const float4*>(b2)[2 * q + 1];
    float4 wl0 = reinterpret_cast<const float4*>(Wlin)[2 * q];
    float4 wl1 = reinterpret_cast<const float4*>(Wlin)[2 * q + 1];
    float dot =
        fmaxf(0.f, s * a[0] + bb0.x) * wl0.x +
        fmaxf(0.f, s * a[1] + bb0.y) * wl0.y +
        fmaxf(0.f, s * a[2] + bb0.z) * wl0.z +
        fmaxf(0.f, s * a[3] + bb0.w) * wl0.w +
        fmaxf(0.f, s * a[4] + bb1.x) * wl1.x +
        fmaxf(0.f, s * a[5] + bb1.y) * wl1.y +
        fmaxf(0.f, s * a[6] + bb1.z) * wl1.z +
        fmaxf(0.f, s * a[7] + bb1.w) * wl1.w;

    #pragma unroll
    for (int o = 4; o; o >>= 1) dot += __shfl_xor_sync(0xFFFFFFFFu, dot, o);
    if (q == 0) {
        int g = __ldg(batch + node);
        atomicAdd(&g_gbuf[g], dot);
        atomicAdd(&g_gbuf[64 + g], 1.0f);
    }
}

// ---------------------------------------------------------------------------
__global__ void k_finalize(const float* __restrict__ blin, float* __restrict__ out) {
    int g = threadIdx.x;
    if (g < 64) out[g] = g_gbuf[g] / fmaxf(g_gbuf[64 + g], 1.0f) + blin[0];
}

// ---------------------------------------------------------------------------
extern "C" void kernel_launch(void* const* d_in, const int* in_sizes, int n_in,
                              void* d_out, int out_size)
{
    const float* x     = (const float*)d_in[0];
    const int*   eidx  = (const int*)d_in[1];
    const int*   batch = (const int*)d_in[2];
    const float* W1    = (const float*)d_in[3];
    const float* b1    = (const float*)d_in[4];
    const float* W2    = (const float*)d_in[5];
    const float* b2    = (const float*)d_in[6];
    const float* Wlin  = (const float*)d_in[7];
    const float* blin  = (const float*)d_in[8];
    float* out = (float*)d_out;

    const int N = in_sizes[0] / 128;   // 50000
    const int E = in_sizes[1] / 2;     // 800000
    const int* src = eidx;
    const int* dst = eidx + E;

    const int T = 256;
    const int NB = (N + 1023) / 1024;

    // one-time host-side resources (no device memory involved)
    static cudaStream_t s2 = nullptr;
    static cudaEvent_t evF = nullptr, evJ = nullptr;
    if (s2 == nullptr) {
        if (cudaStreamCreateWithFlags(&s2, cudaStreamNonBlocking) != cudaSuccess)
            s2 = nullptr;
        cudaEventCreateWithFlags(&evF, cudaEventDisableTiming);
        cudaEventCreateWithFlags(&evJ, cudaEventDisableTiming);
    }

    void* p_ideg = nullptr;
    void* p_gbuf = nullptr;
    cudaGetSymbolAddress(&p_ideg, g_ideg);
    cudaGetSymbolAddress(&p_gbuf, g_gbuf);
    cudaMemsetAsync(p_ideg, 0, NN * sizeof(int));
    cudaMemsetAsync(p_gbuf, 0, 128 * sizeof(float));

    // fork: GEMM1 (unscaled, no dinv dependency) on s2, CSR build on stream 0
    if (s2) {
        cudaEventRecord(evF, 0);
        cudaStreamWaitEvent(s2, evF, 0);
        k_gemm<128, false, false><<<(N + 127) / 128, 256, 0, s2>>>(x, W1, N);
        cudaEventRecord(evJ, s2);
    } else {
        k_gemm<128, false, false><<<(N + 127) / 128, 256>>>(x, W1, N);
    }

    // CSR build + dinv on stream 0
    k_count<<<(E + T - 1) / T, T>>>(dst, E);
    k_scan1<<<NB, 1024>>>(N);
    k_scan3<<<(N + T - 1) / T, T>>>(N);
    k_fill <<<(E + T - 1) / T, T>>>(src, dst, E);

    // join
    if (s2) cudaStreamWaitEvent(0, evJ, 0);

    // layer 1 gather (applies dinv[src] per edge)
    k_gather1<<<(N * 8 + T - 1) / T, T>>>(b1, N);

    // layer 2 (scaled epilogue, dinv available)
    k_gemm<64, true, true><<<(N + 127) / 128, 256>>>(nullptr, W2, N);
    k_gather2<<<(N * 8 + T - 1) / T, T>>>(b2, Wlin, batch, N);

    k_finalize<<<1, 64>>>(blin, out);
}